// round 3
// baseline (speedup 1.0000x reference)
#include <cuda_runtime.h>
#include <math.h>

// Problem dims (fixed by the dataset)
#define B_  64
#define S_  1024
#define I_  1024
#define H_  1024

// ---------------- persistent state (no allocations allowed) ----------------
__device__ float    g_h[2][B_ * H_];   // ping-pong hidden state
__device__ unsigned g_bar;             // grid barrier arrival counter

// ---------------- init: copy h0, reset barrier ----------------
__global__ void init_kernel(const float* __restrict__ h0) {
    int i = blockIdx.x * blockDim.x + threadIdx.x;
    if (i < B_ * H_) g_h[0][i] = h0[i];
    if (i == 0) g_bar = 0u;
}

// ---------------- Phase 1: wx = x @ Wih_w^T + Wih_b  ----------------
// A: [M=B*S, K] row-major (K contiguous); W: [N=H, K] row-major (K contiguous)
// C[m][n] = sum_k A[m][k] * W[n][k] + bias[n]
#define BM 128
#define BN 128
#define BK 8

__global__ __launch_bounds__(256) void gemm_wx_kernel(
    const float* __restrict__ A,
    const float* __restrict__ W,
    const float* __restrict__ bias,
    float* __restrict__ C)
{
    const int K = I_, N = H_;
    __shared__ __align__(16) float As[BK][BM];
    __shared__ __align__(16) float Bs[BK][BN];

    const int bm  = blockIdx.y * BM;
    const int bn  = blockIdx.x * BN;
    const int tid = threadIdx.x;
    const int lr  = tid >> 1;         // 0..127: tile row (A) / tile col (W)
    const int lk  = (tid & 1) << 2;   // 0 or 4: k offset of the float4
    const int tm  = (tid >> 4) << 3;  // 0..120: micro-tile row base
    const int tn  = (tid & 15) << 3;  // 0..120: micro-tile col base

    const float* Ap = A + (size_t)(bm + lr) * K + lk;
    const float* Wp = W + (size_t)(bn + lr) * K + lk;

    float acc[8][8];
    #pragma unroll
    for (int i = 0; i < 8; i++)
        #pragma unroll
        for (int j = 0; j < 8; j++) acc[i][j] = 0.f;

    // register double-buffered global loads
    float4 av = *(const float4*)Ap;
    float4 bv = *(const float4*)Wp;

    for (int k0 = 0; k0 < K; k0 += BK) {
        __syncthreads();
        As[lk + 0][lr] = av.x; As[lk + 1][lr] = av.y;
        As[lk + 2][lr] = av.z; As[lk + 3][lr] = av.w;
        Bs[lk + 0][lr] = bv.x; Bs[lk + 1][lr] = bv.y;
        Bs[lk + 2][lr] = bv.z; Bs[lk + 3][lr] = bv.w;
        if (k0 + BK < K) {
            av = *(const float4*)(Ap + k0 + BK);
            bv = *(const float4*)(Wp + k0 + BK);
        }
        __syncthreads();
        #pragma unroll
        for (int kk = 0; kk < BK; kk++) {
            float4 a0 = *(const float4*)&As[kk][tm];
            float4 a1 = *(const float4*)&As[kk][tm + 4];
            float4 b0 = *(const float4*)&Bs[kk][tn];
            float4 b1 = *(const float4*)&Bs[kk][tn + 4];
            float af[8] = {a0.x, a0.y, a0.z, a0.w, a1.x, a1.y, a1.z, a1.w};
            float bf[8] = {b0.x, b0.y, b0.z, b0.w, b1.x, b1.y, b1.z, b1.w};
            #pragma unroll
            for (int i = 0; i < 8; i++)
                #pragma unroll
                for (int j = 0; j < 8; j++)
                    acc[i][j] += af[i] * bf[j];
        }
    }

    float bi[8];
    #pragma unroll
    for (int j = 0; j < 8; j++) bi[j] = bias[bn + tn + j];

    #pragma unroll
    for (int i = 0; i < 8; i++) {
        size_t row = (size_t)(bm + tm + i);
        float4 o0 = make_float4(acc[i][0] + bi[0], acc[i][1] + bi[1],
                                acc[i][2] + bi[2], acc[i][3] + bi[3]);
        float4 o1 = make_float4(acc[i][4] + bi[4], acc[i][5] + bi[5],
                                acc[i][6] + bi[6], acc[i][7] + bi[7]);
        *(float4*)&C[row * N + bn + tn]     = o0;
        *(float4*)&C[row * N + bn + tn + 4] = o1;
    }
}

// ---------------- Phase 2: persistent recurrent scan ----------------
// 128 resident CTAs; CTA j owns output columns [j*8, j*8+8) with its Whh slice
// resident in SMEM. Per step: h_new[b,g] = tanh(wx[b,t,g] + b[g] + sum_k h[b,k]*Whh[g,k])
// wx is read in place from y and overwritten with the result.
#define NCTA   128
#define CPC    8            // output columns per CTA
#define T2     256          // threads per CTA
#define HCH    64           // h K-chunk staged in smem
#define NCHUNK (H_ / HCH)   // 16

__global__ __launch_bounds__(T2) void rnn_steps_kernel(
    const float* __restrict__ Whh,
    const float* __restrict__ Whh_b,
    float* __restrict__ y,      // [B,S,H], contains wx on entry
    float* __restrict__ hlast)  // [B,H] or nullptr
{
    __shared__ __align__(16) float sW[CPC * H_];  // 32 KB: Whh slice, [c][k] (contig)
    __shared__ __align__(16) float sh[B_ * HCH];  // 16 KB: h chunk [b][k]; reused as stage

    const int cta = blockIdx.x;
    const int tid = threadIdx.x;
    const int g0  = cta * CPC;

    // Load this CTA's Whh slice once (rows g0..g0+7 are contiguous in global).
    for (int v = tid; v < CPC * H_; v += T2)
        sW[v] = Whh[(size_t)g0 * H_ + v];

    // Thread decomposition: ks = K-split lane (8-way), cg = col group (2), bg = batch group (16)
    const int ks = tid & 7;
    const int cg = (tid >> 3) & 1;
    const int bg = tid >> 4;
    const int b0 = bg << 2;   // 4 batches per thread
    const int c0 = cg << 2;   // 4 cols per thread

    const float bi_fin = Whh_b[g0 + (tid & 7)];  // bias for finalize lane (gl = tid&7)

    for (int t = 0; t < S_; t++) {
        const float* hc = g_h[t & 1];
        float*       hn = g_h[(t & 1) ^ 1];

        // Prefetch chunk 0 of h into registers (post-barrier, data is final).
        float4 pf[4];
        #pragma unroll
        for (int i = 0; i < 4; i++) {
            int v = tid + i * T2;          // 0..1023 float4s = 64x64 floats
            int b  = v >> 4;
            int kl = (v & 15) << 2;
            pf[i] = *(const float4*)&hc[(size_t)b * H_ + kl];
        }

        float acc[4][4];
        #pragma unroll
        for (int j = 0; j < 4; j++)
            #pragma unroll
            for (int c = 0; c < 4; c++) acc[j][c] = 0.f;

        #pragma unroll 1
        for (int kc = 0; kc < NCHUNK; kc++) {
            __syncthreads();               // sh free for overwrite
            #pragma unroll
            for (int i = 0; i < 4; i++) {
                int v = tid + i * T2;
                int b  = v >> 4;
                int kl = (v & 15) << 2;
                *(float4*)&sh[b * HCH + kl] = pf[i];
            }
            if (kc + 1 < NCHUNK) {         // prefetch next chunk, hidden under compute
                #pragma unroll
                for (int i = 0; i < 4; i++) {
                    int v = tid + i * T2;
                    int b  = v >> 4;
                    int kl = (v & 15) << 2;
                    pf[i] = *(const float4*)&hc[(size_t)b * H_ + (kc + 1) * HCH + kl];
                }
            }
            __syncthreads();
            const int kgb = kc * HCH;
            #pragma unroll
            for (int i = 0; i < 2; i++) {
                // interleaved K-split: lane ks takes k = i*32 + ks*4 .. +3 (16B lane
                // stride -> conflict-free LDS.128 phases)
                const int klo = (i << 5) + (ks << 2);
                float4 hv[4], wv[4];
                #pragma unroll
                for (int j = 0; j < 4; j++)
                    hv[j] = *(const float4*)&sh[(b0 + j) * HCH + klo];
                #pragma unroll
                for (int c = 0; c < 4; c++)
                    wv[c] = *(const float4*)&sW[(c0 + c) * H_ + kgb + klo];
                #pragma unroll
                for (int j = 0; j < 4; j++)
                    #pragma unroll
                    for (int c = 0; c < 4; c++) {
                        acc[j][c] += hv[j].x * wv[c].x;
                        acc[j][c] += hv[j].y * wv[c].y;
                        acc[j][c] += hv[j].z * wv[c].z;
                        acc[j][c] += hv[j].w * wv[c].w;
                    }
            }
        }

        // Reduce the 8-way K-split: ks lanes are adjacent -> butterfly within 8-lane groups.
        #pragma unroll
        for (int j = 0; j < 4; j++)
            #pragma unroll
            for (int c = 0; c < 4; c++) {
                float v = acc[j][c];
                v += __shfl_xor_sync(0xFFFFFFFFu, v, 1);
                v += __shfl_xor_sync(0xFFFFFFFFu, v, 2);
                v += __shfl_xor_sync(0xFFFFFFFFu, v, 4);
                acc[j][c] = v;
            }

        __syncthreads();                    // done reading sh (chunk data)
        // Stage 512 sums into sh for coalesced finalize (2 values per thread).
        #pragma unroll
        for (int q = 0; q < 2; q++) {
            int p = (ks << 1) + q;          // 0..15 within the (bg,cg) group
            int j = p >> 2, c = p & 3;
            sh[(b0 + j) * CPC + (c0 + c)] = acc[j][c];
        }
        __syncthreads();

        // Finalize: read wx in place, tanh, write y / h_next (/ h_last).
        #pragma unroll
        for (int q = 0; q < 2; q++) {
            int o  = tid + q * T2;          // 0..511
            int b  = o >> 3;
            int gl = o & 7;                 // == tid&7 for both q -> bi_fin valid
            size_t yi = ((size_t)b * S_ + t) * H_ + g0 + gl;
            float val = tanhf(y[yi] + bi_fin + sh[o]);
            y[yi] = val;
            hn[(size_t)b * H_ + g0 + gl] = val;
            if (hlast && t == S_ - 1) hlast[(size_t)b * H_ + g0 + gl] = val;
        }

        // Grid barrier: monotone-target arrival counter (reset by init_kernel).
        __threadfence();
        __syncthreads();
        if (tid == 0) {
            atomicAdd(&g_bar, 1u);
            const unsigned target = (unsigned)(t + 1) * (unsigned)NCTA;
            while (*((volatile unsigned*)&g_bar) < target) { __nanosleep(64); }
            __threadfence();
        }
        __syncthreads();
    }
}

// ---------------- launch ----------------
extern "C" void kernel_launch(void* const* d_in, const int* in_sizes, int n_in,
                              void* d_out, int out_size) {
    (void)in_sizes; (void)n_in;
    const float* x     = (const float*)d_in[0];
    const float* h0    = (const float*)d_in[1];
    const float* Wih_w = (const float*)d_in[2];
    const float* Wih_b = (const float*)d_in[3];
    const float* Whh_w = (const float*)d_in[4];
    const float* Whh_b = (const float*)d_in[5];

    float* out   = (float*)d_out;
    float* y     = out;                              // [B,S,H]
    float* hlast = nullptr;                          // [B,H] appended if present
    const long long ybsh = (long long)B_ * S_ * H_;
    if ((long long)out_size >= ybsh + (long long)B_ * H_)
        hlast = out + ybsh;

    // 1) init hidden state + barrier
    init_kernel<<<(B_ * H_ + 255) / 256, 256>>>(h0);

    // 2) wx = x @ Wih^T + b, written into y region
    dim3 g1(H_ / BN, (B_ * S_) / BM);
    gemm_wx_kernel<<<g1, 256>>>(x, Wih_w, Wih_b, y);

    // 3) persistent recurrent scan (128 resident CTAs, internal grid barrier)
    rnn_steps_kernel<<<NCTA, T2>>>(Whh_w, Whh_b, y, hlast);
}

// round 8
// speedup vs baseline: 1.1601x; 1.1601x over previous
#include <cuda_runtime.h>
#include <cuda_bf16.h>
#include <math.h>
#include <stdint.h>

// Problem dims (fixed by the dataset)
#define B_  64
#define S_  1024
#define I_  1024
#define H_  1024

// =================== base-ISA PTX helpers (no sm_103a-only features) ===========
__device__ __forceinline__ uint32_t smem_u32(const void* p) {
    uint32_t a;
    asm("{ .reg .u64 t; cvta.to.shared.u64 t, %1; cvt.u32.u64 %0, t; }"
        : "=r"(a) : "l"(p));
    return a;
}
__device__ __forceinline__ void cp_async16(uint32_t saddr, const void* gaddr) {
    asm volatile("cp.async.cg.shared.global [%0], [%1], 16;"
                 :: "r"(saddr), "l"(gaddr));
}
__device__ __forceinline__ void cp_commit() {
    asm volatile("cp.async.commit_group;" ::: "memory");
}
template <int N>
__device__ __forceinline__ void cp_wait() {
    asm volatile("cp.async.wait_group %0;" :: "n"(N) : "memory");
}
__device__ __forceinline__ void ldsm4(uint32_t* r, uint32_t a) {
    asm volatile("ldmatrix.sync.aligned.m8n8.x4.shared.b16 {%0,%1,%2,%3}, [%4];"
                 : "=r"(r[0]), "=r"(r[1]), "=r"(r[2]), "=r"(r[3]) : "r"(a));
}
__device__ __forceinline__ void ldsm2(uint32_t* r, uint32_t a) {
    asm volatile("ldmatrix.sync.aligned.m8n8.x2.shared.b16 {%0,%1}, [%2];"
                 : "=r"(r[0]), "=r"(r[1]) : "r"(a));
}
// D(f32) += A(bf16) * B(bf16)^T, m16n8k16
__device__ __forceinline__ void mma16816(float* c, const uint32_t* a, const uint32_t* b) {
    asm volatile(
        "mma.sync.aligned.m16n8k16.row.col.f32.bf16.bf16.f32 "
        "{%0,%1,%2,%3}, {%4,%5,%6,%7}, {%8,%9}, {%0,%1,%2,%3};"
        : "+f"(c[0]), "+f"(c[1]), "+f"(c[2]), "+f"(c[3])
        : "r"(a[0]), "r"(a[1]), "r"(a[2]), "r"(a[3]), "r"(b[0]), "r"(b[1]));
}

// =================== persistent state (no allocations allowed) ===================
__device__ float    g_h[2][B_ * H_];   // ping-pong hidden state
__device__ unsigned g_bar;             // grid barrier arrival counter
// bf16-split scratch for phase-1 tensor-core GEMM
__device__ __nv_bfloat16 g_xhi[(size_t)B_ * S_ * I_];
__device__ __nv_bfloat16 g_xlo[(size_t)B_ * S_ * I_];
__device__ __nv_bfloat16 g_whi[(size_t)H_ * I_];
__device__ __nv_bfloat16 g_wlo[(size_t)H_ * I_];

// =================== init: copy h0, reset barrier ===================
__global__ void init_kernel(const float* __restrict__ h0) {
    int i = blockIdx.x * blockDim.x + threadIdx.x;
    if (i < B_ * H_) g_h[0][i] = h0[i];
    if (i == 0) g_bar = 0u;
}

// =================== fp32 -> (hi, lo) bf16 split ===================
__global__ void convert_x_kernel(const float* __restrict__ src) {
    size_t i = (size_t)blockIdx.x * blockDim.x + threadIdx.x;   // one float4
    float4 v = ((const float4*)src)[i];
    __nv_bfloat16 hx = __float2bfloat16(v.x), hy = __float2bfloat16(v.y);
    __nv_bfloat16 hz = __float2bfloat16(v.z), hw = __float2bfloat16(v.w);
    __nv_bfloat16 lx = __float2bfloat16(v.x - __bfloat162float(hx));
    __nv_bfloat16 ly = __float2bfloat16(v.y - __bfloat162float(hy));
    __nv_bfloat16 lz = __float2bfloat16(v.z - __bfloat162float(hz));
    __nv_bfloat16 lw = __float2bfloat16(v.w - __bfloat162float(hw));
    __nv_bfloat162* dh = ((__nv_bfloat162*)g_xhi) + 2 * i;
    __nv_bfloat162* dl = ((__nv_bfloat162*)g_xlo) + 2 * i;
    dh[0] = __halves2bfloat162(hx, hy); dh[1] = __halves2bfloat162(hz, hw);
    dl[0] = __halves2bfloat162(lx, ly); dl[1] = __halves2bfloat162(lz, lw);
}
__global__ void convert_w_kernel(const float* __restrict__ src) {
    size_t i = (size_t)blockIdx.x * blockDim.x + threadIdx.x;
    float4 v = ((const float4*)src)[i];
    __nv_bfloat16 hx = __float2bfloat16(v.x), hy = __float2bfloat16(v.y);
    __nv_bfloat16 hz = __float2bfloat16(v.z), hw = __float2bfloat16(v.w);
    __nv_bfloat16 lx = __float2bfloat16(v.x - __bfloat162float(hx));
    __nv_bfloat16 ly = __float2bfloat16(v.y - __bfloat162float(hy));
    __nv_bfloat16 lz = __float2bfloat16(v.z - __bfloat162float(hz));
    __nv_bfloat16 lw = __float2bfloat16(v.w - __bfloat162float(hw));
    __nv_bfloat162* dh = ((__nv_bfloat162*)g_whi) + 2 * i;
    __nv_bfloat162* dl = ((__nv_bfloat162*)g_wlo) + 2 * i;
    dh[0] = __halves2bfloat162(hx, hy); dh[1] = __halves2bfloat162(hz, hw);
    dl[0] = __halves2bfloat162(lx, ly); dl[1] = __halves2bfloat162(lz, lw);
}

// =================== Phase 1: mma.sync bf16-split GEMM ===================
// wx[m][n] = sum_k x[m][k]*Wih[n][k] + bias[n], 3 bf16 passes (hh + hl + lh).
// Block tile 128x128, BK=16; 8 warps as 2(m) x 4(n), warp tile 64x32.
// Smem: 2 stages x 4 tiles (Ah,Al,Bh,Bl) of 128 rows x 24 elems (48B stride,
// conflict-free ldmatrix: bank-group (3r)%8 is a permutation) = 48 KB static.
#define BKE   16
#define LDT   24
#define TILE_E (128 * LDT)          // 3072 elems = 6144 B
#define NKC   (I_ / BKE)            // 64

__global__ __launch_bounds__(256) void gemm_wx_mma(const float* __restrict__ bias,
                                                   float* __restrict__ C) {
    __shared__ __nv_bfloat16 stg[2][4][TILE_E];   // 49152 B

    const int tid = threadIdx.x;
    const int wid = tid >> 5, lid = tid & 31;
    const int wm = wid >> 2, wn = wid & 3;        // 2 x 4 warps
    const int m0 = blockIdx.y * 128, n0 = blockIdx.x * 128;
    const uint32_t sb = smem_u32(stg);

    // cp.async geometry: thread -> (tile, 2 rows, 2 segs)
    const int ltile = tid >> 6;                   // 0..3
    const int lrow2 = (tid & 63) * 2;             // row base (2 rows per thread)

    // ldmatrix per-lane offsets (bytes within a tile)
    const int grp = lid >> 3, li8 = lid & 7;
    uint32_t offA[4], offB[4];
    #pragma unroll
    for (int f = 0; f < 4; f++)
        offA[f] = (uint32_t)((wm * 64 + f * 16 + li8 + (grp & 1) * 8) * 48 + (grp >> 1) * 16);
    #pragma unroll
    for (int nf = 0; nf < 4; nf++)
        offB[nf] = (uint32_t)((wn * 32 + nf * 8 + li8) * 48 + (grp & 1) * 16);

    float acc[4][4][4];
    #pragma unroll
    for (int f = 0; f < 4; f++)
        #pragma unroll
        for (int nf = 0; nf < 4; nf++)
            #pragma unroll
            for (int q = 0; q < 4; q++) acc[f][nf][q] = 0.f;

    auto load_stage = [&](int kc, int s) {
        const int koff = kc * BKE;
        #pragma unroll
        for (int i = 0; i < 4; i++) {
            const int row = lrow2 + (i >> 1), seg = i & 1;
            const __nv_bfloat16* gp;
            if      (ltile == 0) gp = g_xhi + (size_t)(m0 + row) * I_ + koff + seg * 8;
            else if (ltile == 1) gp = g_xlo + (size_t)(m0 + row) * I_ + koff + seg * 8;
            else if (ltile == 2) gp = g_whi + (size_t)(n0 + row) * I_ + koff + seg * 8;
            else                 gp = g_wlo + (size_t)(n0 + row) * I_ + koff + seg * 8;
            uint32_t sa = sb + (uint32_t)(((s * 4 + ltile) * TILE_E + row * LDT + seg * 8) * 2);
            cp_async16(sa, gp);
        }
        cp_commit();
    };

    load_stage(0, 0);

    for (int kc = 0; kc < NKC; kc++) {
        const int s = kc & 1;
        if (kc + 1 < NKC) { load_stage(kc + 1, s ^ 1); cp_wait<1>(); }
        else             { cp_wait<0>(); }
        __syncthreads();

        const uint32_t base = sb + (uint32_t)(s * 4 * TILE_E * 2);
        const uint32_t tAh = base, tAl = base + 6144, tBh = base + 12288, tBl = base + 18432;

        uint32_t Ah[4][4], Al[4][4], Bh[4][2], Bl[4][2];
        #pragma unroll
        for (int f = 0; f < 4; f++) { ldsm4(Ah[f], tAh + offA[f]); ldsm4(Al[f], tAl + offA[f]); }
        #pragma unroll
        for (int nf = 0; nf < 4; nf++) { ldsm2(Bh[nf], tBh + offB[nf]); ldsm2(Bl[nf], tBl + offB[nf]); }

        #pragma unroll
        for (int f = 0; f < 4; f++)
            #pragma unroll
            for (int nf = 0; nf < 4; nf++) {
                mma16816(acc[f][nf], Ah[f], Bh[nf]);
                mma16816(acc[f][nf], Ah[f], Bl[nf]);
                mma16816(acc[f][nf], Al[f], Bh[nf]);
            }
        __syncthreads();
    }

    // epilogue: add bias, direct coalesced-ish float2 stores
    #pragma unroll
    for (int nf = 0; nf < 4; nf++) {
        const int col = n0 + wn * 32 + nf * 8 + (lid & 3) * 2;
        const float bx = bias[col], by = bias[col + 1];
        #pragma unroll
        for (int f = 0; f < 4; f++) {
            const size_t r0 = (size_t)(m0 + wm * 64 + f * 16 + (lid >> 2));
            float* cp = C + r0 * H_ + col;
            float2 v0 = make_float2(acc[f][nf][0] + bx, acc[f][nf][1] + by);
            float2 v1 = make_float2(acc[f][nf][2] + bx, acc[f][nf][3] + by);
            *(float2*)cp = v0;
            *(float2*)(cp + (size_t)8 * H_) = v1;
        }
    }
}

// =================== Phase 2: persistent recurrent scan ===================
// 128 resident CTAs; CTA j owns output columns [j*8, j*8+8) with its Whh slice
// in SMEM. 8-batch x 4-col x 16-way-K-split register tile, scalar FFMA.
#define NCTA   128
#define CPC    8
#define T2     256
#define HCH    64
#define NCHUNK (H_ / HCH)

__global__ __launch_bounds__(T2) void rnn_steps_kernel(
    const float* __restrict__ Whh,
    const float* __restrict__ Whh_b,
    float* __restrict__ y,      // [B,S,H], contains wx on entry
    float* __restrict__ hlast)  // [B,H] or nullptr
{
    __shared__ __align__(16) float sW[CPC * H_];  // 32 KB
    __shared__ __align__(16) float sh[B_ * HCH];  // 16 KB (chunk + staging reuse)

    const int cta = blockIdx.x, tid = threadIdx.x;
    const int g0 = cta * CPC;
    for (int v = tid; v < CPC * H_; v += T2)
        sW[v] = Whh[(size_t)g0 * H_ + v];

    const int ks = tid & 15;            // 16-way K split
    const int cg = (tid >> 4) & 1;      // 2 col groups of 4
    const int bg = tid >> 5;            // 8 batch groups of 8
    const int b0 = bg << 3;
    const int c0 = cg << 2;
    const int klo = ks << 2;            // 4 k per lane per chunk
    const float bi_fin = Whh_b[g0 + (tid & 7)];

    for (int t = 0; t < S_; t++) {
        const float* hc = g_h[t & 1];
        float*       hn = g_h[(t & 1) ^ 1];

        float4 pf[4];
        #pragma unroll
        for (int i = 0; i < 4; i++) {
            int v = tid + i * T2, b = v >> 4, kl = (v & 15) << 2;
            pf[i] = *(const float4*)&hc[(size_t)b * H_ + kl];
        }

        float acc[8][4];
        #pragma unroll
        for (int j = 0; j < 8; j++)
            #pragma unroll
            for (int c = 0; c < 4; c++) acc[j][c] = 0.f;

        #pragma unroll 1
        for (int kc = 0; kc < NCHUNK; kc++) {
            __syncthreads();
            #pragma unroll
            for (int i = 0; i < 4; i++) {
                int v = tid + i * T2, b = v >> 4, kl = (v & 15) << 2;
                *(float4*)&sh[b * HCH + kl] = pf[i];
            }
            if (kc + 1 < NCHUNK) {
                #pragma unroll
                for (int i = 0; i < 4; i++) {
                    int v = tid + i * T2, b = v >> 4, kl = (v & 15) << 2;
                    pf[i] = *(const float4*)&hc[(size_t)b * H_ + (kc + 1) * HCH + kl];
                }
            }
            __syncthreads();
            const int kgb = kc * HCH;
            float4 wv[4];
            #pragma unroll
            for (int c = 0; c < 4; c++)
                wv[c] = *(const float4*)&sW[(c0 + c) * H_ + kgb + klo];
            #pragma unroll
            for (int j = 0; j < 8; j++) {
                float4 hv = *(const float4*)&sh[(b0 + j) * HCH + klo];
                #pragma unroll
                for (int c = 0; c < 4; c++) {
                    acc[j][c] += hv.x * wv[c].x;
                    acc[j][c] += hv.y * wv[c].y;
                    acc[j][c] += hv.z * wv[c].z;
                    acc[j][c] += hv.w * wv[c].w;
                }
            }
        }

        // reduce 16-way K split (xor 1,2,4,8 within 16-lane groups)
        #pragma unroll
        for (int j = 0; j < 8; j++)
            #pragma unroll
            for (int c = 0; c < 4; c++) {
                float v = acc[j][c];
                v += __shfl_xor_sync(0xFFFFFFFFu, v, 1);
                v += __shfl_xor_sync(0xFFFFFFFFu, v, 2);
                v += __shfl_xor_sync(0xFFFFFFFFu, v, 4);
                v += __shfl_xor_sync(0xFFFFFFFFu, v, 8);
                acc[j][c] = v;
            }

        __syncthreads();
        if (ks == 0) {
            #pragma unroll
            for (int j = 0; j < 8; j++)
                #pragma unroll
                for (int c = 0; c < 4; c++)
                    sh[(b0 + j) * CPC + (c0 + c)] = acc[j][c];
        }
        __syncthreads();

        // finalize: wx in place, tanh, write y / h_next (/ h_last)
        #pragma unroll
        for (int q = 0; q < 2; q++) {
            int o = tid + q * T2;
            int b = o >> 3, gl = o & 7;
            size_t yi = ((size_t)b * S_ + t) * H_ + g0 + gl;
            float val = tanhf(y[yi] + bi_fin + sh[o]);
            y[yi] = val;
            hn[(size_t)b * H_ + g0 + gl] = val;
            if (hlast && t == S_ - 1) hlast[(size_t)b * H_ + g0 + gl] = val;
        }

        // grid barrier: monotone-target arrival counter
        __threadfence();
        __syncthreads();
        if (tid == 0) {
            atomicAdd(&g_bar, 1u);
            const unsigned target = (unsigned)(t + 1) * (unsigned)NCTA;
            while (*((volatile unsigned*)&g_bar) < target) { __nanosleep(32); }
            __threadfence();
        }
        __syncthreads();
    }
}

// =================== launch ===================
extern "C" void kernel_launch(void* const* d_in, const int* in_sizes, int n_in,
                              void* d_out, int out_size) {
    (void)in_sizes; (void)n_in;
    const float* x     = (const float*)d_in[0];
    const float* h0    = (const float*)d_in[1];
    const float* Wih_w = (const float*)d_in[2];
    const float* Wih_b = (const float*)d_in[3];
    const float* Whh_w = (const float*)d_in[4];
    const float* Whh_b = (const float*)d_in[5];

    float* out   = (float*)d_out;
    float* y     = out;
    float* hlast = nullptr;
    const long long ybsh = (long long)B_ * S_ * H_;
    if ((long long)out_size >= ybsh + (long long)B_ * H_)
        hlast = out + ybsh;

    // 1) init hidden state + barrier
    init_kernel<<<(B_ * H_ + 255) / 256, 256>>>(h0);

    // 2) bf16 hi/lo split of x and Wih
    convert_x_kernel<<<(B_ * S_ * I_ / 4) / 256, 256>>>(x);
    convert_w_kernel<<<(H_ * I_ / 4) / 256, 256>>>(Wih_w);

    // 3) wx = x @ Wih^T + b via mma.sync bf16 split (3 passes), into y
    dim3 gg(H_ / 128, (B_ * S_) / 128);   // x-fastest: N-tiles share A panel in L2
    gemm_wx_mma<<<gg, 256>>>(Wih_b, y);

    // 4) persistent recurrent scan
    rnn_steps_kernel<<<NCTA, T2>>>(Whh_w, Whh_b, y, hlast);
}